// round 15
// baseline (speedup 1.0000x reference)
#include <cuda_runtime.h>
#include <cuda_bf16.h>

// SimplePatchScorer: x (512,3,224,224) f32, W (1,768) f32, b (1,) f32
// out (512,196) f32.
//
// f = t*588 + e; t = i*16 + j; e = band*14 + wn (42 bands; band float4 index
// = band*896 + i*56 + wn*4 + jp). row = f/768, k = f mod 768.
//
// R15 (base = R14, 54.0us):
//  (1) CTA = (image, ihalf) owning rows ihalf*98..+97 (128*588 = 98*768),
//      1024 CTAs x 128 thr, occ 7 -> ~99% wave balance (R14-proven).
//  (2) Pair patch rows il and il+4 inside the half: 64*588 = 49*768 ->
//      identical weight/index/predicate sequence, rows +49. Two float4
//      streams per weight fetch: instr/byte x0.75, weight-LDS/byte x0.5,
//      8 lines in flight per thread (unroll 4 x 2 streams).
//  (3) e parity split (R5): e = 147q + p + 2n, linear, wraps 768 once.
//  (4) __launch_bounds__(128,7): 73-reg cap keeps occ 7 (R11/R12 lesson:
//      protect both warps AND batch).
//  (5) LDG.128 + __ldcs, doubled swizzled weights, dual-accumulator
//      predicated FMA, 16 shared atomics/thread.

#define BATCH    512
#define NROWS    196
#define KLEN     768
#define IMG_F4   37632           // 3*224*224/4
#define SW2SZ    1584            // 1536 + 1536/32
#define TPB      128

__global__ __launch_bounds__(TPB, 7)
void patch_scorer_kernel(const float* __restrict__ x,
                         const float* __restrict__ W,
                         const float* __restrict__ bias,
                         float* __restrict__ out)
{
    __shared__ float sW2s[SW2SZ];    // sW2s[a + (a>>5)] = W[a % 768], a<1536
    __shared__ float sAcc[100];      // 98 local rows + pad for zero hi-adds

    const int tid   = threadIdx.x;
    const int b     = blockIdx.x >> 1;   // image
    const int ihalf = blockIdx.x & 1;    // patch-row half

    #pragma unroll
    for (int a = tid; a < 2 * KLEN; a += TPB) {
        const int k = (a < KLEN) ? a : a - KLEN;
        sW2s[a + (a >> 5)] = W[k];
    }
    if (tid < 100) sAcc[tid] = 0.0f;
    __syncthreads();

    const int q  = tid >> 5;         // e-quarter 0..3 (warp id)
    const int p  = (tid >> 4) & 1;   // e parity
    const int il = (tid >> 2) & 3;   // pair id: streams il and il+4
    const int jp = tid & 3;          // float4 group (j = 4jp..4jp+3)

    const int tb = il * 16 + jp * 4; // t_local of element m=0, stream A
    const int E0 = q * 147 + p;      // first e of this thread

    // per-element m: local f, row, k-start (shared by streams A and B)
    const int f0 = tb * 588 + E0;
    const int R0 = f0 / KLEN;        // stream A rows (0..48); B = +49
    const int R1 = (f0 +  588) / KLEN;
    const int R2 = (f0 + 1176) / KLEN;
    const int R3 = (f0 + 1764) / KLEN;
    int a0 = f0          - R0 * KLEN;
    int a1 = (f0 +  588) - R1 * KLEN;
    int a2 = (f0 + 1176) - R2 * KLEN;
    int a3 = (f0 + 1764) - R3 * KLEN;

    int band = E0 / 14;
    int wn   = E0 - band * 14;
    int off  = band * 896 + wn * 4;  // float4 offset within image
    const int trip = 74 - p;         // 74 even steps, 73 odd

    const int iA = ihalf * 8 + il;   // patch rows: A = iA, B = iA + 4
    const float4* pA = (const float4*)x + (size_t)b * IMG_F4 + iA * 56 + jp;
    const float4* pB = pA + 224;     // +4 patch rows = 4*56 float4

    float lA0 = 0.f, lA1 = 0.f, lA2 = 0.f, lA3 = 0.f;
    float hA0 = 0.f, hA1 = 0.f, hA2 = 0.f, hA3 = 0.f;
    float lB0 = 0.f, lB1 = 0.f, lB2 = 0.f, lB3 = 0.f;
    float hB0 = 0.f, hB1 = 0.f, hB2 = 0.f, hB3 = 0.f;

    #pragma unroll 4
    for (int n = 0; n < trip; ++n) {
        const float4 vA = __ldcs(&pA[off]);
        const float4 vB = __ldcs(&pB[off]);

        const float w0 = sW2s[a0 + (a0 >> 5)];
        const float w1 = sW2s[a1 + (a1 >> 5)];
        const float w2 = sW2s[a2 + (a2 >> 5)];
        const float w3 = sW2s[a3 + (a3 >> 5)];

        if (a0 < KLEN) { lA0 += vA.x * w0; lB0 += vB.x * w0; }
        else           { hA0 += vA.x * w0; hB0 += vB.x * w0; }
        if (a1 < KLEN) { lA1 += vA.y * w1; lB1 += vB.y * w1; }
        else           { hA1 += vA.y * w1; hB1 += vB.y * w1; }
        if (a2 < KLEN) { lA2 += vA.z * w2; lB2 += vB.z * w2; }
        else           { hA2 += vA.z * w2; hB2 += vB.z * w2; }
        if (a3 < KLEN) { lA3 += vA.w * w3; lB3 += vB.w * w3; }
        else           { hA3 += vA.w * w3; hB3 += vB.w * w3; }

        a0 += 2; a1 += 2; a2 += 2; a3 += 2;
        off += 8;
        wn += 2;
        if (wn >= 14) { wn -= 14; off += 840; }   // next band
    }

    atomicAdd(&sAcc[R0     ], lA0);
    atomicAdd(&sAcc[R0 +  1], hA0);
    atomicAdd(&sAcc[R1     ], lA1);
    atomicAdd(&sAcc[R1 +  1], hA1);
    atomicAdd(&sAcc[R2     ], lA2);
    atomicAdd(&sAcc[R2 +  1], hA2);
    atomicAdd(&sAcc[R3     ], lA3);
    atomicAdd(&sAcc[R3 +  1], hA3);
    atomicAdd(&sAcc[R0 + 49], lB0);
    atomicAdd(&sAcc[R0 + 50], hB0);
    atomicAdd(&sAcc[R1 + 49], lB1);
    atomicAdd(&sAcc[R1 + 50], hB1);
    atomicAdd(&sAcc[R2 + 49], lB2);
    atomicAdd(&sAcc[R2 + 50], hB2);
    atomicAdd(&sAcc[R3 + 49], lB3);
    atomicAdd(&sAcc[R3 + 50], hB3);

    __syncthreads();

    if (tid < 98)
        out[(size_t)b * NROWS + ihalf * 98 + tid] = sAcc[tid] + bias[0];
}

extern "C" void kernel_launch(void* const* d_in, const int* in_sizes, int n_in,
                              void* d_out, int out_size)
{
    const float* x  = (const float*)d_in[0];   // (512,3,224,224)
    const float* W  = (const float*)d_in[1];   // (1,768)
    const float* bv = (const float*)d_in[2];   // (1,)
    float* out = (float*)d_out;                // (512,196)

    patch_scorer_kernel<<<BATCH * 2, TPB>>>(x, W, bv, out);
}